// round 6
// baseline (speedup 1.0000x reference)
#include <cuda_runtime.h>
#include <cstdint>
#include <math.h>

// Problem constants (fixed shapes)
#define N_ST   2048
#define N_OBS  8192
#define T_LEN  8192

#define N_BLOCKS        128
#define COLS_PER_BLOCK  16          // 2048 / 128
#define THREADS         256
#define KITER           32          // j-values per thread (32 * 64 stripes = 2048)

// ---- persistent device scratch (no allocations allowed) ----
__device__ float        g_Bobs[(size_t)T_LEN * N_ST];  // 64 MB: Bobs[t][i] = B[i][se[t]]
__device__ float        g_alpha[2][N_ST];              // double-buffered alpha
__device__ unsigned int g_flags[N_BLOCKS];             // per-CTA progress: epoch*8192 + t
__device__ unsigned int g_epoch;                       // bumped once per launch

// ---------------------------------------------------------------------------
// Sync primitives (scalar, morally-strong, scope gpu)
// ---------------------------------------------------------------------------
__device__ __forceinline__ unsigned int ld_acquire_u32(const unsigned int* p) {
    unsigned int v;
    asm volatile("ld.acquire.gpu.global.u32 %0, [%1];" : "=r"(v) : "l"(p) : "memory");
    return v;
}
__device__ __forceinline__ void st_release_u32(unsigned int* p, unsigned int v) {
    asm volatile("st.release.gpu.global.u32 [%0], %1;" :: "l"(p), "r"(v) : "memory");
}

// ---------------------------------------------------------------------------
// Kernel 1: gather emissions + bump epoch
// ---------------------------------------------------------------------------
__global__ void gather_bobs(const float* __restrict__ B, const int* __restrict__ se) {
    if (blockIdx.x == 0 && threadIdx.x == 0) g_epoch = g_epoch + 1u;
    size_t idx    = (size_t)blockIdx.x * blockDim.x + threadIdx.x;
    size_t stride = (size_t)gridDim.x * blockDim.x;
    const size_t total = (size_t)T_LEN * N_ST;
    for (; idx < total; idx += stride) {
        int t = (int)(idx >> 11);
        int i = (int)(idx & (N_ST - 1));
        g_Bobs[idx] = B[(size_t)i * N_OBS + se[t]];
    }
}

// ---------------------------------------------------------------------------
// Kernel 2: persistent forward recursion.
// CTA b owns columns [16b, 16b+16). A-slice in registers (32 x float4/thread).
// Sync: per-CTA release-store flags (no atomics), 128 parallel acquire pollers.
// Matvec identical to the R3-proven formulation.
// ---------------------------------------------------------------------------
__global__ void __launch_bounds__(THREADS, 1)
hmm_forward(const float* __restrict__ Pi0,
            const float* __restrict__ A,
            float* __restrict__ out)
{
    __shared__ float alpha_s[N_ST];
    __shared__ float red_s[8 * COLS_PER_BLOCK];   // [warp][16 cols]

    const int tid     = threadIdx.x;
    const int b       = blockIdx.x;
    const int colbase = b * COLS_PER_BLOCK;
    const int lane    = tid & 31;
    const int warp    = tid >> 5;
    const int c       = tid & 3;    // float4 column group (cols 4c..4c+3)
    const int s       = tid >> 2;   // j-stripe id, 0..63

    const unsigned int base = g_epoch << 13;      // epoch * 8192

    // ---- one-time: load A slice into registers ----
    float4 Areg[KITER];
    #pragma unroll
    for (int k = 0; k < KITER; ++k) {
        int j = s + (k << 6);
        Areg[k] = *(const float4*)(A + (size_t)j * N_ST + colbase + (c << 2));
    }

    // ---- step 0: alpha0 = Pi0 * Bobs[0] ----
    if (tid < COLS_PER_BLOCK) {
        int i = colbase + tid;
        __stcg(&g_alpha[0][i], Pi0[i] * g_Bobs[i]);
    }
    __syncthreads();
    if (tid == 0) {
        __threadfence();
        st_release_u32(&g_flags[b], base);        // published step 0
    }

    // ---- steps 1 .. T-1 ----
    for (int t = 1; t < T_LEN; ++t) {
        // emission weights (independent of alpha) -> issue early
        float bt = 0.0f;
        if (tid < COLS_PER_BLOCK)
            bt = __ldg(&g_Bobs[(size_t)t * N_ST + colbase + tid]);

        // wait: every CTA published step t-1 (128 parallel acquire pollers)
        const unsigned int tgt = base + (unsigned int)(t - 1);
        if (tid < N_BLOCKS) {
            while (ld_acquire_u32(&g_flags[tid]) < tgt) { }
        }
        __syncthreads();

        // stage alpha_{t-1} into SMEM (L2-coherent loads)
        {
            const float4* src = (const float4*)g_alpha[(t - 1) & 1];
            float4 v0 = __ldcv(src + tid);
            float4 v1 = __ldcv(src + tid + THREADS);
            ((float4*)alpha_s)[tid]           = v0;
            ((float4*)alpha_s)[tid + THREADS] = v1;
        }
        __syncthreads();

        // matvec partial (R3-proven): acc[e] += alpha[s+64k] * A[s+64k][4c+e]
        float4 acc = make_float4(0.f, 0.f, 0.f, 0.f);
        #pragma unroll
        for (int k = 0; k < KITER; ++k) {
            float a = alpha_s[s + (k << 6)];
            acc.x = fmaf(a, Areg[k].x, acc.x);
            acc.y = fmaf(a, Areg[k].y, acc.y);
            acc.z = fmaf(a, Areg[k].z, acc.z);
            acc.w = fmaf(a, Areg[k].w, acc.w);
        }

        // reduce across the 8 lanes sharing the same c (xor over lane bits 2..4)
        #pragma unroll
        for (int off = 4; off < 32; off <<= 1) {
            acc.x += __shfl_xor_sync(0xffffffffu, acc.x, off);
            acc.y += __shfl_xor_sync(0xffffffffu, acc.y, off);
            acc.z += __shfl_xor_sync(0xffffffffu, acc.z, off);
            acc.w += __shfl_xor_sync(0xffffffffu, acc.w, off);
        }
        if (lane < 4) {   // lane == c here
            int o = (warp << 4) + (lane << 2);
            red_s[o + 0] = acc.x;
            red_s[o + 1] = acc.y;
            red_s[o + 2] = acc.z;
            red_s[o + 3] = acc.w;
        }
        __syncthreads();

        // final per-column sum over 8 warps, apply emission, publish
        if (tid < COLS_PER_BLOCK) {
            float sum = 0.f;
            #pragma unroll
            for (int w = 0; w < 8; ++w) sum += red_s[(w << 4) + tid];
            __stcg(&g_alpha[t & 1][colbase + tid], sum * bt);
        }
        __syncthreads();
        if (tid == 0) {
            __threadfence();
            st_release_u32(&g_flags[b], base + (unsigned int)t);   // published step t
        }
    }

    // ---- final reduction by CTA 0 ----
    if (b == 0) {
        const unsigned int tgt = base + (unsigned int)(T_LEN - 1);
        if (tid < N_BLOCKS) {
            while (ld_acquire_u32(&g_flags[tid]) < tgt) { }
        }
        __syncthreads();

        const float* src = g_alpha[(T_LEN - 1) & 1];
        float ssum = 0.f;
        for (int i = tid; i < N_ST; i += THREADS) ssum += __ldcv(&src[i]);
        #pragma unroll
        for (int off = 16; off > 0; off >>= 1)
            ssum += __shfl_xor_sync(0xffffffffu, ssum, off);
        if (lane == 0) red_s[warp] = ssum;
        __syncthreads();
        if (tid == 0) {
            float tot = 0.f;
            #pragma unroll
            for (int w = 0; w < 8; ++w) tot += red_s[w];
            out[0] = -logf(tot);
        }
    }
}

// ---------------------------------------------------------------------------
// Launch wrapper. Inputs (metadata order): Pi_0 [2048] f32, A [2048*2048] f32,
// B [2048*8192] f32, se [8192] i32. Output: 1 x f32.
// ---------------------------------------------------------------------------
extern "C" void kernel_launch(void* const* d_in, const int* in_sizes, int n_in,
                              void* d_out, int out_size) {
    const float* Pi0 = (const float*)d_in[0];
    const float* A   = (const float*)d_in[1];
    const float* B   = (const float*)d_in[2];
    const int*   se  = (const int*)d_in[3];
    float*       out = (float*)d_out;

    (void)in_sizes; (void)n_in; (void)out_size;

    gather_bobs<<<2048, 256>>>(B, se);
    hmm_forward<<<N_BLOCKS, THREADS>>>(Pi0, A, out);
}

// round 7
// speedup vs baseline: 2.5353x; 2.5353x over previous
#include <cuda_runtime.h>
#include <cstdint>
#include <math.h>

// Problem constants (fixed shapes)
#define N_ST   2048
#define N_OBS  8192
#define T_LEN  8192

#define N_BLOCKS        128
#define COLS_PER_BLOCK  16          // 2048 / 128
#define THREADS         256
#define KITER           32          // j-values per thread (32 * 64 stripes = 2048)
#define ELEMS_PER_THR   8           // 2048 / 256 poll elements per thread

// ---- persistent device scratch (no allocations allowed) ----
__device__ float              g_Bobs[(size_t)T_LEN * N_ST];   // 64 MB
__device__ unsigned long long g_alpha2[2][N_ST];              // {tag:u32 | value:f32} words
__device__ unsigned int       g_epoch;                        // bumped once per launch

// ---------------------------------------------------------------------------
// Scalar morally-strong 8B accessors (single-copy atomic by PTX memory model)
// ---------------------------------------------------------------------------
__device__ __forceinline__ unsigned long long ld_relaxed_u64(const unsigned long long* p) {
    unsigned long long v;
    asm volatile("ld.relaxed.gpu.global.b64 %0, [%1];" : "=l"(v) : "l"(p));
    return v;
}
__device__ __forceinline__ void st_relaxed_u64(unsigned long long* p, unsigned long long v) {
    asm volatile("st.relaxed.gpu.global.b64 [%0], %1;" :: "l"(p), "l"(v) : "memory");
}
__device__ __forceinline__ unsigned long long pack_val_tag(float v, unsigned int tag) {
    return ((unsigned long long)tag << 32) | (unsigned long long)__float_as_uint(v);
}

// ---------------------------------------------------------------------------
// Kernel 1: gather emissions + bump epoch
// ---------------------------------------------------------------------------
__global__ void gather_bobs(const float* __restrict__ B, const int* __restrict__ se) {
    if (blockIdx.x == 0 && threadIdx.x == 0) g_epoch = g_epoch + 1u;
    size_t idx    = (size_t)blockIdx.x * blockDim.x + threadIdx.x;
    size_t stride = (size_t)gridDim.x * blockDim.x;
    const size_t total = (size_t)T_LEN * N_ST;
    for (; idx < total; idx += stride) {
        int t = (int)(idx >> 11);
        int i = (int)(idx & (N_ST - 1));
        g_Bobs[idx] = B[(size_t)i * N_OBS + se[t]];
    }
}

// ---------------------------------------------------------------------------
// Kernel 2: persistent forward recursion, tag-in-data sync via scalar b64.
// CTA b owns columns [16b, 16b+16). A-slice in registers (32 x float4/thread).
// ---------------------------------------------------------------------------
__global__ void __launch_bounds__(THREADS, 1)
hmm_forward(const float* __restrict__ Pi0,
            const float* __restrict__ A,
            float* __restrict__ out)
{
    __shared__ float alpha_s[N_ST];
    __shared__ float red_s[8 * COLS_PER_BLOCK];   // [warp][16 cols]

    const int tid     = threadIdx.x;
    const int b       = blockIdx.x;
    const int colbase = b * COLS_PER_BLOCK;
    const int lane    = tid & 31;
    const int warp    = tid >> 5;
    const int c       = tid & 3;    // float4 column group (cols 4c..4c+3)
    const int s       = tid >> 2;   // j-stripe id, 0..63

    const unsigned int base = g_epoch << 13;      // epoch * 8192

    // ---- one-time: load A slice into registers ----
    float4 Areg[KITER];
    #pragma unroll
    for (int k = 0; k < KITER; ++k) {
        int j = s + (k << 6);
        Areg[k] = *(const float4*)(A + (size_t)j * N_ST + colbase + (c << 2));
    }

    // ---- step 0: alpha0 = Pi0 * Bobs[0], tag = base+0 ----
    if (tid < COLS_PER_BLOCK) {
        int i = colbase + tid;
        st_relaxed_u64(&g_alpha2[0][i], pack_val_tag(Pi0[i] * g_Bobs[i], base));
    }

    // ---- steps 1 .. T-1 ----
    for (int t = 1; t < T_LEN; ++t) {
        // emission weights (independent of alpha) -> issue early
        float bt = 0.0f;
        if (tid < COLS_PER_BLOCK)
            bt = __ldg(&g_Bobs[(size_t)t * N_ST + colbase + tid]);

        // ---- poll alpha_{t-1}: tag + value in the same 8B word ----
        {
            const unsigned int want = base + (unsigned int)(t - 1);
            const unsigned long long* src = &g_alpha2[(t - 1) & 1][tid * ELEMS_PER_THR];
            unsigned long long v[ELEMS_PER_THR];
            for (;;) {
                #pragma unroll
                for (int i = 0; i < ELEMS_PER_THR; ++i) v[i] = ld_relaxed_u64(src + i);
                bool ok = true;
                #pragma unroll
                for (int i = 0; i < ELEMS_PER_THR; ++i)
                    ok &= ((unsigned int)(v[i] >> 32) == want);
                if (ok) break;
            }
            #pragma unroll
            for (int i = 0; i < ELEMS_PER_THR; ++i)
                alpha_s[tid * ELEMS_PER_THR + i] = __uint_as_float((unsigned int)v[i]);
        }
        __syncthreads();

        // ---- matvec partial (R3-proven): acc[e] += alpha[s+64k]*A[s+64k][4c+e]
        float4 acc = make_float4(0.f, 0.f, 0.f, 0.f);
        #pragma unroll
        for (int k = 0; k < KITER; ++k) {
            float a = alpha_s[s + (k << 6)];
            acc.x = fmaf(a, Areg[k].x, acc.x);
            acc.y = fmaf(a, Areg[k].y, acc.y);
            acc.z = fmaf(a, Areg[k].z, acc.z);
            acc.w = fmaf(a, Areg[k].w, acc.w);
        }

        // reduce across the 8 lanes sharing the same c (xor 4,8,16)
        #pragma unroll
        for (int off = 4; off < 32; off <<= 1) {
            acc.x += __shfl_xor_sync(0xffffffffu, acc.x, off);
            acc.y += __shfl_xor_sync(0xffffffffu, acc.y, off);
            acc.z += __shfl_xor_sync(0xffffffffu, acc.z, off);
            acc.w += __shfl_xor_sync(0xffffffffu, acc.w, off);
        }
        if (lane < 4) {   // lane == c here
            int o = (warp << 4) + (lane << 2);
            red_s[o + 0] = acc.x;
            red_s[o + 1] = acc.y;
            red_s[o + 2] = acc.z;
            red_s[o + 3] = acc.w;
        }
        __syncthreads();

        // final per-column sum over 8 warps, apply emission, publish with tag
        if (tid < COLS_PER_BLOCK) {
            float sum = 0.f;
            #pragma unroll
            for (int w = 0; w < 8; ++w) sum += red_s[(w << 4) + tid];
            st_relaxed_u64(&g_alpha2[t & 1][colbase + tid],
                           pack_val_tag(sum * bt, base + (unsigned int)t));
        }
        __syncthreads();   // protect alpha_s / red_s reuse next iteration
    }

    // ---- final reduction by CTA 0 ----
    if (b == 0) {
        const unsigned int want = base + (unsigned int)(T_LEN - 1);
        const unsigned long long* src = &g_alpha2[(T_LEN - 1) & 1][tid * ELEMS_PER_THR];
        float ssum = 0.f;
        {
            unsigned long long v[ELEMS_PER_THR];
            for (;;) {
                #pragma unroll
                for (int i = 0; i < ELEMS_PER_THR; ++i) v[i] = ld_relaxed_u64(src + i);
                bool ok = true;
                #pragma unroll
                for (int i = 0; i < ELEMS_PER_THR; ++i)
                    ok &= ((unsigned int)(v[i] >> 32) == want);
                if (ok) break;
            }
            #pragma unroll
            for (int i = 0; i < ELEMS_PER_THR; ++i)
                ssum += __uint_as_float((unsigned int)v[i]);
        }
        #pragma unroll
        for (int off = 16; off > 0; off >>= 1)
            ssum += __shfl_xor_sync(0xffffffffu, ssum, off);
        if (lane == 0) red_s[warp] = ssum;
        __syncthreads();
        if (tid == 0) {
            float tot = 0.f;
            #pragma unroll
            for (int w = 0; w < 8; ++w) tot += red_s[w];
            out[0] = -logf(tot);
        }
    }
}

// ---------------------------------------------------------------------------
// Launch wrapper. Inputs (metadata order): Pi_0 [2048] f32, A [2048*2048] f32,
// B [2048*8192] f32, se [8192] i32. Output: 1 x f32.
// ---------------------------------------------------------------------------
extern "C" void kernel_launch(void* const* d_in, const int* in_sizes, int n_in,
                              void* d_out, int out_size) {
    const float* Pi0 = (const float*)d_in[0];
    const float* A   = (const float*)d_in[1];
    const float* B   = (const float*)d_in[2];
    const int*   se  = (const int*)d_in[3];
    float*       out = (float*)d_out;

    (void)in_sizes; (void)n_in; (void)out_size;

    gather_bobs<<<2048, 256>>>(B, se);
    hmm_forward<<<N_BLOCKS, THREADS>>>(Pi0, A, out);
}